// round 14
// baseline (speedup 1.0000x reference)
#include <cuda_runtime.h>

#define BATCH   128
#define NN      100
#define DD      128
#define ITILE   20          // i-rows per CTA (100/20 = 5 tiles per batch)
#define NTILES  5
#define PITCH   132         // >= DD, and PITCH/4 == 33 ≡ 1 (mod 8): conflict-free row reads
#define THREADS 512
#define MASKV   (-9e15f)
#define NEG_BIG (-3.4e38f)

// smem (floats): Hs 100*132 | At 3*132 | Bt 9*132 | sA 20*100 | sB 20*100 = 18784 fl = 75.1 KB
#define SMEM_FLOATS (NN*PITCH + 3*PITCH + 9*PITCH + 2*ITILE*NN)
#define SMEM_BYTES  (SMEM_FLOATS * 4)

typedef unsigned long long u64t;

// packed fp32x2 helpers (sm_100+): 2 IEEE fp32 ops per instruction
__device__ __forceinline__ u64t mul2(u64t a, u64t b) {
    u64t r;
    asm("mul.rn.f32x2 %0, %1, %2;" : "=l"(r) : "l"(a), "l"(b));
    return r;
}
__device__ __forceinline__ void fma2(u64t& acc, u64t a, u64t b) {
    asm("fma.rn.f32x2 %0, %1, %2, %0;" : "+l"(acc) : "l"(a), "l"(b));
}
__device__ __forceinline__ float hsum2(u64t v) {
    float lo, hi;
    asm("mov.b64 {%0, %1}, %2;" : "=f"(lo), "=f"(hi) : "l"(v));
    return lo + hi;
}

extern "C" __global__ void __launch_bounds__(THREADS, 2)
la_kernel(const float* __restrict__ hidden,
          const int*   __restrict__ adj,
          const int*   __restrict__ beh,
          const float* __restrict__ A,
          const float* __restrict__ Bm,
          float*       __restrict__ out)
{
    extern __shared__ float smem[];
    float* Hs = smem;
    float* At = Hs + NN*PITCH;
    float* Bt = At + 3*PITCH;
    float* sA = Bt + 9*PITCH;
    float* sB = sA + ITILE*NN;

    const int tid = threadIdx.x;
    const int b   = blockIdx.x / NTILES;
    const int i0  = (blockIdx.x % NTILES) * ITILE;

    // ---- stage hidden[b] (pitched, float4) ----
    {
        const float4* hg = (const float4*)(hidden + (size_t)b * NN * DD);
        for (int v = tid; v < NN * (DD/4); v += THREADS) {
            int j = v >> 5;                       // DD/4 == 32
            int qq = v & 31;
            *(float4*)&Hs[j * PITCH + qq * 4] = hg[j * (DD/4) + qq];
        }
    }
    // ---- stage A,Bm transposed ----
    for (int t = tid; t < DD*3; t += THREADS) {
        int d = t / 3, k = t - d*3;
        At[k * PITCH + d] = A[t];
    }
    for (int t = tid; t < DD*9; t += THREADS) {
        int d = t / 9, k = t - d*9;
        Bt[k * PITCH + d] = Bm[t];
    }
    __syncthreads();

    // ---- score phase: 2i x 2j per thread, gathered-A + gathered-B, f32x2 math ----
    if (tid < 500) {
        const int p = tid / 50;                   // i-group 0..9  -> rows p, p+10
        const int q = tid - p * 50;               // j-group 0..49 -> cols q, q+50
        const int* adjB = adj + (size_t)b * NN * NN;
        const int* behB = beh + (size_t)b * NN * NN;

        unsigned vaPack = 0, vbPack = 0;
        const float* ap[2][2];
        const float* bp[2][2];
        #pragma unroll
        for (int t = 0; t < 2; t++) {
            int i = i0 + p + 10*t;
            #pragma unroll
            for (int s = 0; s < 2; s++) {
                int j  = q + 50*s;
                int ca = adjB[i * NN + j];
                int cb = behB[i * NN + j];
                int ia = min(max(ca - 1, 0), 2);
                int ib = min(max(cb - 1, 0), 8);
                int k  = t*2 + s;
                vaPack |= (unsigned)((ca >= 1) & (ca <= 3)) << k;
                vbPack |= (unsigned)(cb >= 1) << k;
                ap[t][s] = &At[ia * PITCH];
                bp[t][s] = &Bt[ib * PITCH];
            }
        }
        const float* hiP0 = &Hs[(i0 + p)      * PITCH];
        const float* hiP1 = &Hs[(i0 + p + 10) * PITCH];

        u64t accA[2][2], accB[2][2];
        #pragma unroll
        for (int t = 0; t < 2; t++)
            #pragma unroll
            for (int s = 0; s < 2; s++)
                accA[t][s] = accB[t][s] = 0ull;

        #pragma unroll 1
        for (int d = 0; d < DD; d += 4) {
            ulonglong2 hi[2], hj[2];
            hi[0] = *(const ulonglong2*)(hiP0 + d);
            hi[1] = *(const ulonglong2*)(hiP1 + d);
            hj[0] = *(const ulonglong2*)&Hs[ q       * PITCH + d];
            hj[1] = *(const ulonglong2*)&Hs[(q + 50) * PITCH + d];
            // batch all gathers up front for MLP
            ulonglong2 av[2][2], bv[2][2];
            #pragma unroll
            for (int t = 0; t < 2; t++)
                #pragma unroll
                for (int s = 0; s < 2; s++) {
                    av[t][s] = *(const ulonglong2*)(ap[t][s] + d);   // 3-row gather (near-broadcast)
                    bv[t][s] = *(const ulonglong2*)(bp[t][s] + d);   // 9-row gather
                }
            #pragma unroll
            for (int t = 0; t < 2; t++) {
                #pragma unroll
                for (int s = 0; s < 2; s++) {
                    u64t plo = mul2(hi[t].x, hj[s].x);
                    u64t phi = mul2(hi[t].y, hj[s].y);
                    fma2(accA[t][s], plo, av[t][s].x); fma2(accA[t][s], phi, av[t][s].y);
                    fma2(accB[t][s], plo, bv[t][s].x); fma2(accB[t][s], phi, bv[t][s].y);
                }
            }
        }

        #pragma unroll
        for (int t = 0; t < 2; t++) {
            int il = p + 10*t;
            #pragma unroll
            for (int s = 0; s < 2; s++) {
                int j = q + 50*s;
                int k = t*2 + s;
                float va = hsum2(accA[t][s]);
                float vb = hsum2(accB[t][s]);
                va = va >= 0.f ? va : 0.2f * va;       // LeakyReLU(0.2)
                vb = vb >= 0.f ? vb : 0.2f * vb;
                sA[il * NN + j] = ((vaPack >> k) & 1) ? va : MASKV;
                sB[il * NN + j] = ((vbPack >> k) & 1) ? vb : MASKV;
            }
        }
    }
    __syncthreads();

    // ---- dual softmax + combine: sA[row] = 0.5*softmax(sA) + 0.5*softmax(sB) ----
    {
        int w = tid >> 5, lane = tid & 31;
        for (int r = w; r < ITILE; r += THREADS/32) {
            float* rowA = &sA[r * NN];
            float* rowB = &sB[r * NN];
            float va[4], vb[4];
            float mA = NEG_BIG, mB = NEG_BIG;
            #pragma unroll
            for (int u = 0; u < 4; u++) {
                int j = lane + 32*u;
                va[u] = (j < NN) ? rowA[j] : NEG_BIG;
                vb[u] = (j < NN) ? rowB[j] : NEG_BIG;
                mA = fmaxf(mA, va[u]);
                mB = fmaxf(mB, vb[u]);
            }
            #pragma unroll
            for (int o = 16; o > 0; o >>= 1) {
                mA = fmaxf(mA, __shfl_xor_sync(0xffffffffu, mA, o));
                mB = fmaxf(mB, __shfl_xor_sync(0xffffffffu, mB, o));
            }
            float sAcc = 0.f, sBcc = 0.f;
            #pragma unroll
            for (int u = 0; u < 4; u++) {
                int j = lane + 32*u;
                if (j < NN) {
                    va[u] = __expf(va[u] - mA); sAcc += va[u];
                    vb[u] = __expf(vb[u] - mB); sBcc += vb[u];
                }
            }
            #pragma unroll
            for (int o = 16; o > 0; o >>= 1) {
                sAcc += __shfl_xor_sync(0xffffffffu, sAcc, o);
                sBcc += __shfl_xor_sync(0xffffffffu, sBcc, o);
            }
            float invA = 0.5f / sAcc;     // GAMMA folded
            float invB = 0.5f / sBcc;
            #pragma unroll
            for (int u = 0; u < 4; u++) {
                int j = lane + 32*u;
                if (j < NN) rowA[j] = va[u] * invA + vb[u] * invB;
            }
        }
    }
    __syncthreads();

    // ---- output: 2 i-rows per thread (il, il+10); j unrolled x4 with uniform
    //      float4 weight loads ----
    if (tid < (ITILE/2) * (DD/4)) {           // 320 active threads
        int il = tid >> 5;                    // 0..9 (uniform per warp)
        int d4 = (tid & 31) * 4;
        const float* w1 = &sA[ il       * NN];
        const float* w2 = &sA[(il + 10) * NN];
        float4 acc1 = make_float4(0.f,0.f,0.f,0.f);
        float4 acc2 = make_float4(0.f,0.f,0.f,0.f);
        #pragma unroll 1
        for (int j = 0; j < NN; j += 4) {
            float4 wv1 = *(const float4*)&w1[j];     // uniform per warp
            float4 wv2 = *(const float4*)&w2[j];     // uniform per warp
            float4 hv0 = *(const float4*)&Hs[(j+0) * PITCH + d4];
            float4 hv1 = *(const float4*)&Hs[(j+1) * PITCH + d4];
            float4 hv2 = *(const float4*)&Hs[(j+2) * PITCH + d4];
            float4 hv3 = *(const float4*)&Hs[(j+3) * PITCH + d4];
            acc1.x = fmaf(wv1.x, hv0.x, acc1.x);
            acc1.y = fmaf(wv1.x, hv0.y, acc1.y);
            acc1.z = fmaf(wv1.x, hv0.z, acc1.z);
            acc1.w = fmaf(wv1.x, hv0.w, acc1.w);
            acc2.x = fmaf(wv2.x, hv0.x, acc2.x);
            acc2.y = fmaf(wv2.x, hv0.y, acc2.y);
            acc2.z = fmaf(wv2.x, hv0.z, acc2.z);
            acc2.w = fmaf(wv2.x, hv0.w, acc2.w);
            acc1.x = fmaf(wv1.y, hv1.x, acc1.x);
            acc1.y = fmaf(wv1.y, hv1.y, acc1.y);
            acc1.z = fmaf(wv1.y, hv1.z, acc1.z);
            acc1.w = fmaf(wv1.y, hv1.w, acc1.w);
            acc2.x = fmaf(wv2.y, hv1.x, acc2.x);
            acc2.y = fmaf(wv2.y, hv1.y, acc2.y);
            acc2.z = fmaf(wv2.y, hv1.z, acc2.z);
            acc2.w = fmaf(wv2.y, hv1.w, acc2.w);
            acc1.x = fmaf(wv1.z, hv2.x, acc1.x);
            acc1.y = fmaf(wv1.z, hv2.y, acc1.y);
            acc1.z = fmaf(wv1.z, hv2.z, acc1.z);
            acc1.w = fmaf(wv1.z, hv2.w, acc1.w);
            acc2.x = fmaf(wv2.z, hv2.x, acc2.x);
            acc2.y = fmaf(wv2.z, hv2.y, acc2.y);
            acc2.z = fmaf(wv2.z, hv2.z, acc2.z);
            acc2.w = fmaf(wv2.z, hv2.w, acc2.w);
            acc1.x = fmaf(wv1.w, hv3.x, acc1.x);
            acc1.y = fmaf(wv1.w, hv3.y, acc1.y);
            acc1.z = fmaf(wv1.w, hv3.z, acc1.z);
            acc1.w = fmaf(wv1.w, hv3.w, acc1.w);
            acc2.x = fmaf(wv2.w, hv3.x, acc2.x);
            acc2.y = fmaf(wv2.w, hv3.y, acc2.y);
            acc2.z = fmaf(wv2.w, hv3.z, acc2.z);
            acc2.w = fmaf(wv2.w, hv3.w, acc2.w);
        }
        float* og = out + (size_t)b * NN * DD;
        *(float4*)&og[(i0 + il)      * DD + d4] = acc1;
        *(float4*)&og[(i0 + il + 10) * DD + d4] = acc2;
    }
}

extern "C" void kernel_launch(void* const* d_in, const int* in_sizes, int n_in,
                              void* d_out, int out_size)
{
    const float* hidden = (const float*)d_in[0];
    const int*   adj    = (const int*)  d_in[1];
    const int*   beh    = (const int*)  d_in[2];
    const float* A      = (const float*)d_in[3];
    const float* Bm     = (const float*)d_in[4];
    float*       out    = (float*)d_out;

    cudaFuncSetAttribute(la_kernel,
                         cudaFuncAttributeMaxDynamicSharedMemorySize,
                         SMEM_BYTES);

    dim3 grid(BATCH * NTILES);    // 640 CTAs
    la_kernel<<<grid, THREADS, SMEM_BYTES>>>(hidden, adj, beh, A, Bm, out);
}

// round 15
// speedup vs baseline: 1.1562x; 1.1562x over previous
#include <cuda_runtime.h>

#define BATCH   128
#define NN      100
#define DD      128
#define ITILE   10          // i-rows per CTA (100/10 = 10 tiles per batch)
#define NTILES  10
#define PITCH   132         // PITCH/4 == 33 ≡ 1 (mod 8): consecutive rows -> distinct quad-bank groups
#define THREADS 256
#define MASKV   (-9e15f)
#define NEG_BIG (-3.4e38f)

// smem (floats): Hs 100*132 | At 3*132 | Bt 9*132 | sA 10*100 | sB 10*100  = 65.6 KB
#define SMEM_FLOATS (NN*PITCH + 3*PITCH + 9*PITCH + 2*ITILE*NN)
#define SMEM_BYTES  (SMEM_FLOATS * 4)

typedef unsigned long long u64t;

// packed fp32x2 helpers (sm_100+): 2 IEEE fp32 ops per instruction
__device__ __forceinline__ u64t mul2(u64t a, u64t b) {
    u64t r;
    asm("mul.rn.f32x2 %0, %1, %2;" : "=l"(r) : "l"(a), "l"(b));
    return r;
}
__device__ __forceinline__ void fma2(u64t& acc, u64t a, u64t b) {
    asm("fma.rn.f32x2 %0, %1, %2, %0;" : "+l"(acc) : "l"(a), "l"(b));
}
__device__ __forceinline__ float hsum2(u64t v) {
    float lo, hi;
    asm("mov.b64 {%0, %1}, %2;" : "=f"(lo), "=f"(hi) : "l"(v));
    return lo + hi;
}

extern "C" __global__ void __launch_bounds__(THREADS, 3)
la_kernel(const float* __restrict__ hidden,
          const int*   __restrict__ adj,
          const int*   __restrict__ beh,
          const float* __restrict__ A,
          const float* __restrict__ Bm,
          float*       __restrict__ out)
{
    extern __shared__ float smem[];
    float* Hs = smem;
    float* At = Hs + NN*PITCH;
    float* Bt = At + 3*PITCH;
    float* sA = Bt + 9*PITCH;
    float* sB = sA + ITILE*NN;

    const int tid = threadIdx.x;
    const int b   = blockIdx.x / NTILES;
    const int i0  = (blockIdx.x % NTILES) * ITILE;

    // ---- stage hidden[b] (pitched, float4) ----
    {
        const float4* hg = (const float4*)(hidden + (size_t)b * NN * DD);
        for (int v = tid; v < NN * (DD/4); v += THREADS) {
            int j = v >> 5;                       // DD/4 == 32
            int qq = v & 31;
            *(float4*)&Hs[j * PITCH + qq * 4] = hg[j * (DD/4) + qq];
        }
    }
    // ---- stage A,Bm transposed ----
    for (int t = tid; t < DD*3; t += THREADS) {
        int d = t / 3, k = t - d*3;
        At[k * PITCH + d] = A[t];
    }
    for (int t = tid; t < DD*9; t += THREADS) {
        int d = t / 9, k = t - d*9;
        Bt[k * PITCH + d] = Bm[t];
    }
    __syncthreads();

    // ---- score phase: 2i x 2j per thread, dense-A (3 ch) + gathered-B, f32x2 math ----
    // unroll 2: lets ptxas software-pipeline iteration k+1's LDS under iteration k's FMAs
    if (tid < 250) {
        const int p = tid / 50;                   // i-group 0..4  -> rows p, p+5
        const int q = tid - p * 50;               // j-group 0..49 -> cols q, q+50
        const int* adjB = adj + (size_t)b * NN * NN;
        const int* behB = beh + (size_t)b * NN * NN;

        unsigned iaPack = 0, vaPack = 0, vbPack = 0;
        const float* bp[2][2];
        #pragma unroll
        for (int t = 0; t < 2; t++) {
            int i = i0 + p + 5*t;
            #pragma unroll
            for (int s = 0; s < 2; s++) {
                int j  = q + 50*s;
                int ca = adjB[i * NN + j];
                int cb = behB[i * NN + j];
                int ia = min(max(ca - 1, 0), 2);
                int ib = min(max(cb - 1, 0), 8);
                int k  = t*2 + s;
                iaPack |= (unsigned)ia << (2*k);
                vaPack |= (unsigned)((ca >= 1) & (ca <= 3)) << k;
                vbPack |= (unsigned)(cb >= 1) << k;
                bp[t][s] = &Bt[ib * PITCH];
            }
        }
        const float* hiP0 = &Hs[(i0 + p)     * PITCH];
        const float* hiP1 = &Hs[(i0 + p + 5) * PITCH];

        u64t a0c[2][2], a1c[2][2], a2c[2][2], bAc[2][2];
        #pragma unroll
        for (int t = 0; t < 2; t++)
            #pragma unroll
            for (int s = 0; s < 2; s++)
                a0c[t][s] = a1c[t][s] = a2c[t][s] = bAc[t][s] = 0ull;

        #pragma unroll 2
        for (int d = 0; d < DD; d += 4) {
            ulonglong2 w0 = *(const ulonglong2*)&At[d];             // broadcast
            ulonglong2 w1 = *(const ulonglong2*)&At[PITCH   + d];
            ulonglong2 w2 = *(const ulonglong2*)&At[2*PITCH + d];
            ulonglong2 hi[2], hj[2];
            hi[0] = *(const ulonglong2*)(hiP0 + d);
            hi[1] = *(const ulonglong2*)(hiP1 + d);
            hj[0] = *(const ulonglong2*)&Hs[ q       * PITCH + d];
            hj[1] = *(const ulonglong2*)&Hs[(q + 50) * PITCH + d];
            #pragma unroll
            for (int t = 0; t < 2; t++) {
                #pragma unroll
                for (int s = 0; s < 2; s++) {
                    ulonglong2 bv = *(const ulonglong2*)(bp[t][s] + d); // gather (9 rows)
                    u64t plo = mul2(hi[t].x, hj[s].x);
                    u64t phi = mul2(hi[t].y, hj[s].y);
                    fma2(a0c[t][s], plo, w0.x); fma2(a0c[t][s], phi, w0.y);
                    fma2(a1c[t][s], plo, w1.x); fma2(a1c[t][s], phi, w1.y);
                    fma2(a2c[t][s], plo, w2.x); fma2(a2c[t][s], phi, w2.y);
                    fma2(bAc[t][s], plo, bv.x); fma2(bAc[t][s], phi, bv.y);
                }
            }
        }

        #pragma unroll
        for (int t = 0; t < 2; t++) {
            int il = p + 5*t;
            #pragma unroll
            for (int s = 0; s < 2; s++) {
                int j = q + 50*s;
                int k = t*2 + s;
                int ia = (iaPack >> (2*k)) & 3;
                u64t sel = (ia == 0) ? a0c[t][s] : (ia == 1) ? a1c[t][s] : a2c[t][s];
                float va = hsum2(sel);
                float vb = hsum2(bAc[t][s]);
                va = va >= 0.f ? va : 0.2f * va;       // LeakyReLU(0.2)
                vb = vb >= 0.f ? vb : 0.2f * vb;
                sA[il * NN + j] = ((vaPack >> k) & 1) ? va : MASKV;
                sB[il * NN + j] = ((vbPack >> k) & 1) ? vb : MASKV;
            }
        }
    }
    __syncthreads();

    // ---- dual softmax + combine: sA[row] = 0.5*softmax(sA) + 0.5*softmax(sB) ----
    {
        int w = tid >> 5, lane = tid & 31;
        for (int r = w; r < ITILE; r += THREADS/32) {
            float* rowA = &sA[r * NN];
            float* rowB = &sB[r * NN];
            float va[4], vb[4];
            float mA = NEG_BIG, mB = NEG_BIG;
            #pragma unroll
            for (int u = 0; u < 4; u++) {
                int j = lane + 32*u;
                va[u] = (j < NN) ? rowA[j] : NEG_BIG;
                vb[u] = (j < NN) ? rowB[j] : NEG_BIG;
                mA = fmaxf(mA, va[u]);
                mB = fmaxf(mB, vb[u]);
            }
            #pragma unroll
            for (int o = 16; o > 0; o >>= 1) {
                mA = fmaxf(mA, __shfl_xor_sync(0xffffffffu, mA, o));
                mB = fmaxf(mB, __shfl_xor_sync(0xffffffffu, mB, o));
            }
            float sAcc = 0.f, sBcc = 0.f;
            #pragma unroll
            for (int u = 0; u < 4; u++) {
                int j = lane + 32*u;
                if (j < NN) {
                    va[u] = __expf(va[u] - mA); sAcc += va[u];
                    vb[u] = __expf(vb[u] - mB); sBcc += vb[u];
                }
            }
            #pragma unroll
            for (int o = 16; o > 0; o >>= 1) {
                sAcc += __shfl_xor_sync(0xffffffffu, sAcc, o);
                sBcc += __shfl_xor_sync(0xffffffffu, sBcc, o);
            }
            float invA = 0.5f / sAcc;     // GAMMA folded
            float invB = 0.5f / sBcc;
            #pragma unroll
            for (int u = 0; u < 4; u++) {
                int j = lane + 32*u;
                if (j < NN) rowA[j] = va[u] * invA + vb[u] * invB;
            }
        }
    }
    __syncthreads();

    // ---- output: 2 i-rows per thread (il, il+5); j unrolled x4 with uniform
    //      float4 weight loads (1-cyc broadcast) instead of per-j scalars ----
    {
        float* og = out + (size_t)b * NN * DD;
        for (int o = tid; o < (ITILE/2) * (DD/4); o += THREADS) {   // 160 items
            int il = o >> 5;                  // 0..4 (uniform per warp)
            int d4 = (o & 31) * 4;
            const float* w1 = &sA[ il      * NN];
            const float* w2 = &sA[(il + 5) * NN];
            float4 acc1 = make_float4(0.f,0.f,0.f,0.f);
            float4 acc2 = make_float4(0.f,0.f,0.f,0.f);
            #pragma unroll 1
            for (int j = 0; j < NN; j += 4) {
                float4 wv1 = *(const float4*)&w1[j];     // uniform per warp
                float4 wv2 = *(const float4*)&w2[j];     // uniform per warp
                float4 hv0 = *(const float4*)&Hs[(j+0) * PITCH + d4];
                float4 hv1 = *(const float4*)&Hs[(j+1) * PITCH + d4];
                float4 hv2 = *(const float4*)&Hs[(j+2) * PITCH + d4];
                float4 hv3 = *(const float4*)&Hs[(j+3) * PITCH + d4];
                acc1.x = fmaf(wv1.x, hv0.x, acc1.x);
                acc1.y = fmaf(wv1.x, hv0.y, acc1.y);
                acc1.z = fmaf(wv1.x, hv0.z, acc1.z);
                acc1.w = fmaf(wv1.x, hv0.w, acc1.w);
                acc2.x = fmaf(wv2.x, hv0.x, acc2.x);
                acc2.y = fmaf(wv2.x, hv0.y, acc2.y);
                acc2.z = fmaf(wv2.x, hv0.z, acc2.z);
                acc2.w = fmaf(wv2.x, hv0.w, acc2.w);
                acc1.x = fmaf(wv1.y, hv1.x, acc1.x);
                acc1.y = fmaf(wv1.y, hv1.y, acc1.y);
                acc1.z = fmaf(wv1.y, hv1.z, acc1.z);
                acc1.w = fmaf(wv1.y, hv1.w, acc1.w);
                acc2.x = fmaf(wv2.y, hv1.x, acc2.x);
                acc2.y = fmaf(wv2.y, hv1.y, acc2.y);
                acc2.z = fmaf(wv2.y, hv1.z, acc2.z);
                acc2.w = fmaf(wv2.y, hv1.w, acc2.w);
                acc1.x = fmaf(wv1.z, hv2.x, acc1.x);
                acc1.y = fmaf(wv1.z, hv2.y, acc1.y);
                acc1.z = fmaf(wv1.z, hv2.z, acc1.z);
                acc1.w = fmaf(wv1.z, hv2.w, acc1.w);
                acc2.x = fmaf(wv2.z, hv2.x, acc2.x);
                acc2.y = fmaf(wv2.z, hv2.y, acc2.y);
                acc2.z = fmaf(wv2.z, hv2.z, acc2.z);
                acc2.w = fmaf(wv2.z, hv2.w, acc2.w);
                acc1.x = fmaf(wv1.w, hv3.x, acc1.x);
                acc1.y = fmaf(wv1.w, hv3.y, acc1.y);
                acc1.z = fmaf(wv1.w, hv3.z, acc1.z);
                acc1.w = fmaf(wv1.w, hv3.w, acc1.w);
                acc2.x = fmaf(wv2.w, hv3.x, acc2.x);
                acc2.y = fmaf(wv2.w, hv3.y, acc2.y);
                acc2.z = fmaf(wv2.w, hv3.z, acc2.z);
                acc2.w = fmaf(wv2.w, hv3.w, acc2.w);
            }
            *(float4*)&og[(i0 + il)     * DD + d4] = acc1;
            *(float4*)&og[(i0 + il + 5) * DD + d4] = acc2;
        }
    }
}

extern "C" void kernel_launch(void* const* d_in, const int* in_sizes, int n_in,
                              void* d_out, int out_size)
{
    const float* hidden = (const float*)d_in[0];
    const int*   adj    = (const int*)  d_in[1];
    const int*   beh    = (const int*)  d_in[2];
    const float* A      = (const float*)d_in[3];
    const float* Bm     = (const float*)d_in[4];
    float*       out    = (float*)d_out;

    cudaFuncSetAttribute(la_kernel,
                         cudaFuncAttributeMaxDynamicSharedMemorySize,
                         SMEM_BYTES);

    dim3 grid(BATCH * NTILES);    // 1280 CTAs
    la_kernel<<<grid, THREADS, SMEM_BYTES>>>(hidden, adj, beh, A, Bm, out);
}